// round 4
// baseline (speedup 1.0000x reference)
#include <cuda_runtime.h>
#include <cuda_bf16.h>
#include <math.h>
#include <cstdint>

// ---------------- problem constants ----------------
#define NQ      512
#define DIM     256
#define KQ      65536
#define KNN     200
#define NCLS    1000
#define INVT    (1.0f/0.07f)

#define NF      (KQ*DIM)
#define NL      KQ

#define OUT_FEAT_OFF 1
#define OUT_LAB_OFF  (1 + NF)
#define OUT_PTR_OFF  (1 + NF + NL)

// candidate filtering
#define CMAX     4096
#define T_FILTER 0.14f

// ---------------- device scratch ----------------
__device__ float g_sim[(size_t)NQ * KQ];
__device__ unsigned long long g_cand[(size_t)NQ * CMAX];
__device__ int  g_cnt[NQ];
__device__ int  g_correct;

__device__ __forceinline__ unsigned orderf(float f) {
    unsigned u = __float_as_uint(f);
    return (u & 0x80000000u) ? ~u : (u | 0x80000000u);
}

// ---------------- kernel 0 ----------------
__global__ void zero_kernel() {
    int t = threadIdx.x;
    if (t < NQ) g_cnt[t] = 0;
    if (t == 0) g_correct = 0;
}

// ---------------- kernel 1: HMMA (mma.sync bf16) GEMM with 3-term split ----------------
// C[512,65536] = A[512,256] * B[65536,256]^T  into g_sim + candidate lists
#define TM 128
#define TN 128
#define KC 32
#define NCHUNK (DIM / KC)

#define TILE_WORDS (2 * 128 * 8)
#define BUF_WORDS  (4 * TILE_WORDS)
#define GEMM_SMEM  (2 * BUF_WORDS * 4)

__device__ __forceinline__ void mma16816(float* c, const uint32_t* a, const uint32_t* b) {
    asm volatile(
        "mma.sync.aligned.m16n8k16.row.col.f32.bf16.bf16.f32 "
        "{%0,%1,%2,%3}, {%4,%5,%6,%7}, {%8,%9}, {%0,%1,%2,%3};"
        : "+f"(c[0]), "+f"(c[1]), "+f"(c[2]), "+f"(c[3])
        : "r"(a[0]), "r"(a[1]), "r"(a[2]), "r"(a[3]), "r"(b[0]), "r"(b[1]));
}

__device__ __forceinline__ void cappend(int qrow, float v, int col) {
    if (v > T_FILTER) {
        int slot = atomicAdd(&g_cnt[qrow], 1);
        if (slot < CMAX)
            g_cand[(size_t)qrow * CMAX + slot] =
                ((unsigned long long)__float_as_uint(v) << 32) |
                (unsigned)(col ^ 0xFFFF);
    }
}

__global__ void __launch_bounds__(256, 1)
gemm_tc_kernel(const float* __restrict__ A, const float* __restrict__ B) {
    extern __shared__ uint32_t smw[];
    const int tid  = threadIdx.x;
    const int lane = tid & 31;
    const int wid  = tid >> 5;
    const int gID  = lane >> 2;
    const int tig  = lane & 3;
    const int wm   = wid >> 2;
    const int wn   = wid & 3;
    const int tileM = blockIdx.x * TM;
    const int tileN = blockIdx.y * TN;

    float acc[4][4][4];
    #pragma unroll
    for (int m = 0; m < 4; m++)
        #pragma unroll
        for (int n = 0; n < 4; n++)
            #pragma unroll
            for (int r = 0; r < 4; r++) acc[m][n][r] = 0.f;

    float4 ra[4], rb[4];
    {
        #pragma unroll
        for (int i = 0; i < 4; i++) {
            int f = i * 256 + tid;
            int row = f >> 3, k = (f & 7) * 4;
            ra[i] = *(const float4*)(A + (size_t)(tileM + row) * DIM + k);
            rb[i] = *(const float4*)(B + (size_t)(tileN + row) * DIM + k);
        }
    }

    for (int ch = 0; ch < NCHUNK; ++ch) {
        const int buf = ch & 1;
        uint32_t* aw  = smw + buf * BUF_WORDS;
        uint32_t* alw = aw + TILE_WORDS;
        uint32_t* bw  = alw + TILE_WORDS;
        uint32_t* blw = bw + TILE_WORDS;

        #pragma unroll
        for (int i = 0; i < 4; i++) {
            int f = i * 256 + tid;
            int row = f >> 3, k = (f & 7) * 4;
            int k16 = k >> 4;
            int q = (k & 15) >> 1;
            int p0 = ((q & 3) * 2) + (q >> 2);
            int p1 = (((q + 1) & 3) * 2) + ((q + 1) >> 2);
            int base = (k16 * 128 + row) * 8;

            float4 v = ra[i];
            __nv_bfloat162 h0 = __floats2bfloat162_rn(v.x, v.y);
            float2 hf0 = __bfloat1622float2(h0);
            __nv_bfloat162 l0 = __floats2bfloat162_rn(v.x - hf0.x, v.y - hf0.y);
            __nv_bfloat162 h1 = __floats2bfloat162_rn(v.z, v.w);
            float2 hf1 = __bfloat1622float2(h1);
            __nv_bfloat162 l1 = __floats2bfloat162_rn(v.z - hf1.x, v.w - hf1.y);
            aw [base + p0] = *(uint32_t*)&h0;  aw [base + p1] = *(uint32_t*)&h1;
            alw[base + p0] = *(uint32_t*)&l0;  alw[base + p1] = *(uint32_t*)&l1;

            v = rb[i];
            h0 = __floats2bfloat162_rn(v.x, v.y);
            hf0 = __bfloat1622float2(h0);
            l0 = __floats2bfloat162_rn(v.x - hf0.x, v.y - hf0.y);
            h1 = __floats2bfloat162_rn(v.z, v.w);
            hf1 = __bfloat1622float2(h1);
            l1 = __floats2bfloat162_rn(v.z - hf1.x, v.w - hf1.y);
            bw [base + p0] = *(uint32_t*)&h0;  bw [base + p1] = *(uint32_t*)&h1;
            blw[base + p0] = *(uint32_t*)&l0;  blw[base + p1] = *(uint32_t*)&l1;
        }
        __syncthreads();

        if (ch + 1 < NCHUNK) {
            #pragma unroll
            for (int i = 0; i < 4; i++) {
                int f = i * 256 + tid;
                int row = f >> 3, k = (f & 7) * 4 + (ch + 1) * KC;
                ra[i] = *(const float4*)(A + (size_t)(tileM + row) * DIM + k);
                rb[i] = *(const float4*)(B + (size_t)(tileN + row) * DIM + k);
            }
        }

        #pragma unroll
        for (int t = 0; t < 3; t++) {
            const uint32_t* As = (t == 2) ? alw : aw;
            const uint32_t* Bs = (t == 1) ? blw : bw;
            #pragma unroll
            for (int s = 0; s < 2; s++) {
                uint32_t afr[4][4];
                #pragma unroll
                for (int m = 0; m < 4; m++) {
                    int row = wm * 64 + m * 16 + gID;
                    uint2 v0 = *(const uint2*)(As + (s * 128 + row) * 8 + tig * 2);
                    uint2 v1 = *(const uint2*)(As + (s * 128 + row + 8) * 8 + tig * 2);
                    afr[m][0] = v0.x; afr[m][2] = v0.y;
                    afr[m][1] = v1.x; afr[m][3] = v1.y;
                }
                uint32_t bfr[4][2];
                #pragma unroll
                for (int n = 0; n < 4; n++) {
                    int rowb = wn * 32 + n * 8 + gID;
                    uint2 v = *(const uint2*)(Bs + (s * 128 + rowb) * 8 + tig * 2);
                    bfr[n][0] = v.x; bfr[n][1] = v.y;
                }
                #pragma unroll
                for (int m = 0; m < 4; m++)
                    #pragma unroll
                    for (int n = 0; n < 4; n++)
                        mma16816(acc[m][n], afr[m], bfr[n]);
            }
        }
        __syncthreads();
    }

    // epilogue: write sim + filter candidates
    #pragma unroll
    for (int m = 0; m < 4; m++) {
        int row = tileM + wm * 64 + m * 16 + gID;
        #pragma unroll
        for (int n = 0; n < 4; n++) {
            int col = tileN + wn * 32 + n * 8 + tig * 2;
            *(float2*)(g_sim + (size_t)row * KQ + col) =
                make_float2(acc[m][n][0], acc[m][n][1]);
            *(float2*)(g_sim + (size_t)(row + 8) * KQ + col) =
                make_float2(acc[m][n][2], acc[m][n][3]);
            cappend(row,     acc[m][n][0], col);
            cappend(row,     acc[m][n][1], col + 1);
            cappend(row + 8, acc[m][n][2], col);
            cappend(row + 8, acc[m][n][3], col + 1);
        }
    }
}

// ---------------- kernel 2: candidate top-200 + vote + argmax (w/ fallback) ----------------
#define NBINS    16384
#define CAND_MAX 1024
// smem: cand u64[CMAX] @0 (32KB) | hist u32[NBINS] @32768 (64KB) | scores @98304 (4KB)
#define TOPK_SMEM (32768 + 65536 + 4096)

__global__ void __launch_bounds__(256)
topk_kernel(const int* __restrict__ qlabels, const int* __restrict__ labels) {
    extern __shared__ char smem[];
    unsigned long long* cand = (unsigned long long*)smem;
    unsigned* hist = (unsigned*)(smem + 32768);
    float* scores  = (float*)(smem + 32768 + 65536);
    float* cval    = (float*)smem;                 // fallback alias
    int*   clab    = (int*)(smem + 4096);          // fallback alias

    __shared__ unsigned s_gsum[256];
    __shared__ int s_B, s_cGreater, s_cnt;
    __shared__ float s_bv[256];
    __shared__ int   s_bi[256];

    const int tid = threadIdx.x;
    const int q   = blockIdx.x;
    const int cnt = g_cnt[q];

    for (int i = tid; i < 1024; i += 256) scores[i] = 0.f;

    if (cnt >= KNN && cnt <= CMAX) {
        // fast path: exact rank over the candidate set
        for (int i = tid; i < cnt; i += 256)
            cand[i] = g_cand[(size_t)q * CMAX + i];
        __syncthreads();

        for (int i = tid; i < cnt; i += 256) {
            unsigned long long mine = cand[i];
            int rank = 0;
            for (int j = 0; j < cnt; j++) rank += (cand[j] > mine);
            if (rank < KNN) {
                float v = __uint_as_float((unsigned)(mine >> 32));
                int idx = ((int)((unsigned)mine & 0xFFFFu)) ^ 0xFFFF;
                atomicAdd(&scores[qlabels[idx]], expf(v * INVT));
            }
        }
        __syncthreads();
    } else {
        // fallback: histogram select on the full sim row (always correct)
        const float* row = g_sim + (size_t)q * KQ;
        for (int i = tid; i < NBINS; i += 256) hist[i] = 0u;
        if (tid == 0) s_cnt = 0;
        __syncthreads();

        for (int i = tid; i < KQ; i += 256) {
            unsigned u = orderf(row[i]);
            atomicAdd(&hist[u >> 18], 1u);
        }
        __syncthreads();

        unsigned gs = 0;
        #pragma unroll 8
        for (int b = 0; b < 64; b++) gs += hist[tid * 64 + b];
        s_gsum[tid] = gs;
        __syncthreads();

        if (tid == 0) {
            unsigned cum = 0; int B = 0; unsigned cG = 0;
            for (int g = 255; g >= 0; --g) {
                if (cum + s_gsum[g] >= KNN) {
                    for (int b = g * 64 + 63; b >= g * 64; --b) {
                        if (cum + hist[b] >= KNN) { B = b; cG = cum; break; }
                        cum += hist[b];
                    }
                    break;
                }
                cum += s_gsum[g];
            }
            s_B = B; s_cGreater = (int)cG;
        }
        __syncthreads();

        const int B = s_B;
        int need = KNN - s_cGreater;

        for (int i = tid; i < KQ; i += 256) {
            float v = row[i];
            int bin = (int)(orderf(v) >> 18);
            if (bin > B) {
                atomicAdd(&scores[qlabels[i]], expf(v * INVT));
            } else if (bin == B) {
                int p = atomicAdd(&s_cnt, 1);
                if (p < CAND_MAX) { cval[p] = v; clab[p] = qlabels[i]; }
            }
        }
        __syncthreads();

        int bcnt = min(s_cnt, CAND_MAX);
        if (need > bcnt) need = bcnt;

        for (int i = tid; i < bcnt; i += 256) {
            float v = cval[i];
            int rank = 0;
            for (int j = 0; j < bcnt; j++) {
                float w = cval[j];
                rank += (w > v) || (w == v && j < i);
            }
            if (rank < need) atomicAdd(&scores[clab[i]], expf(v * INVT));
        }
        __syncthreads();
    }

    // argmax over 1000 classes, first-max tie-break
    float best = -1.f; int bi = NCLS;
    for (int c = tid; c < NCLS; c += 256) {
        float v = scores[c];
        if (v > best) { best = v; bi = c; }
    }
    s_bv[tid] = best; s_bi[tid] = bi;
    __syncthreads();
    for (int s = 128; s > 0; s >>= 1) {
        if (tid < s) {
            float ov = s_bv[tid + s]; int oi = s_bi[tid + s];
            if (ov > s_bv[tid] || (ov == s_bv[tid] && oi < s_bi[tid])) {
                s_bv[tid] = ov; s_bi[tid] = oi;
            }
        }
        __syncthreads();
    }
    if (tid == 0 && s_bi[0] == labels[q]) atomicAdd(&g_correct, 1);
}

// ---------------- kernel 3: queue update copy ----------------
__global__ void __launch_bounds__(256)
copy_kernel(const float* __restrict__ feats, const int* __restrict__ labels,
            const float* __restrict__ qf, const int* __restrict__ ql,
            const int* __restrict__ qptr, float* __restrict__ out) {
    const int ptr = qptr[0];
    size_t i4 = (size_t)blockIdx.x * 256 + threadIdx.x;
    if (i4 < (size_t)(NF / 4)) {
        int r = (int)(i4 >> 6);
        int rel = r - ptr; if (rel < 0) rel += KQ;
        float4 v = (rel < NQ) ? ((const float4*)feats)[(size_t)rel * 64 + (i4 & 63)]
                              : ((const float4*)qf)[i4];
        float* o = out + OUT_FEAT_OFF + i4 * 4;
        o[0] = v.x; o[1] = v.y; o[2] = v.z; o[3] = v.w;
    } else if (i4 < (size_t)(NF / 4 + NL / 4)) {
        int j4 = (int)(i4 - NF / 4);
        int4 lv = ((const int4*)ql)[j4];
        int base = j4 * 4;
        float* o = out + OUT_LAB_OFF + base;
        #pragma unroll
        for (int k = 0; k < 4; k++) {
            int i = base + k;
            int rel = i - ptr; if (rel < 0) rel += KQ;
            int lab = (rel < NQ) ? labels[rel] : ((const int*)&lv)[k];
            o[k] = (float)lab;
        }
    }
}

// ---------------- kernel 4: scalars ----------------
__global__ void finalize_kernel(const int* __restrict__ qptr, float* __restrict__ out) {
    out[0] = (float)g_correct * (1.0f / (float)NQ);
    out[OUT_PTR_OFF] = (float)((qptr[0] + NQ) % KQ);
}

// ---------------- launch ----------------
extern "C" void kernel_launch(void* const* d_in, const int* in_sizes, int n_in,
                              void* d_out, int out_size) {
    const float* feats  = (const float*)d_in[0];
    const int*   labels = (const int*)d_in[1];
    const float* qf     = (const float*)d_in[2];
    const int*   ql     = (const int*)d_in[3];
    const int*   qptr   = (const int*)d_in[4];
    float* out = (float*)d_out;

    cudaFuncSetAttribute(gemm_tc_kernel, cudaFuncAttributeMaxDynamicSharedMemorySize, GEMM_SMEM);
    cudaFuncSetAttribute(topk_kernel, cudaFuncAttributeMaxDynamicSharedMemorySize, TOPK_SMEM);

    zero_kernel<<<1, 512>>>();
    gemm_tc_kernel<<<dim3(NQ / TM, KQ / TN), 256, GEMM_SMEM>>>(feats, qf);
    topk_kernel<<<NQ, 256, TOPK_SMEM>>>(ql, labels);

    int total4 = NF / 4 + NL / 4;
    copy_kernel<<<(total4 + 255) / 256, 256>>>(feats, labels, qf, ql, qptr, out);
    finalize_kernel<<<1, 1>>>(qptr, out);
    (void)in_sizes; (void)n_in; (void)out_size;
}

// round 5
// speedup vs baseline: 1.3045x; 1.3045x over previous
#include <cuda_runtime.h>
#include <cuda_bf16.h>
#include <math.h>
#include <cstdint>

// ---------------- problem constants ----------------
#define NQ      512
#define DIM     256
#define KQ      65536
#define KNN     200
#define NCLS    1000
#define INVT    (1.0f/0.07f)

#define NF      (KQ*DIM)
#define NL      KQ

#define OUT_FEAT_OFF 1
#define OUT_LAB_OFF  (1 + NF)
#define OUT_PTR_OFF  (1 + NF + NL)

// candidate filtering
#define CMAX     4096
#define T_FILTER 0.14f

// ---------------- device scratch ----------------
__device__ float g_sim[(size_t)NQ * KQ];                 // fallback scratch only
__device__ unsigned long long g_cand[(size_t)NQ * CMAX];
__device__ int  g_cnt[NQ];
__device__ int  g_correct;

// pre-converted bf16 hi/lo operands, tile-sequential permuted layout:
// group g = (tile*16 + k16)*128 + row ; 8 u32 words per group (permuted k-pairs)
__device__ uint32_t g_Ah[65536],  g_Al[65536];           // A: 4 tiles
__device__ uint32_t g_Bh[(size_t)8388608], g_Bl[(size_t)8388608]; // B: 512 tiles

__device__ __forceinline__ unsigned orderf(float f) {
    unsigned u = __float_as_uint(f);
    return (u & 0x80000000u) ? ~u : (u | 0x80000000u);
}

#define CP16(dst, src) \
    asm volatile("cp.async.cg.shared.global [%0], [%1], 16;" :: "r"(dst), "l"(src) : "memory")
#define CPCOMMIT() asm volatile("cp.async.commit_group;" ::: "memory")

__device__ __forceinline__ uint32_t smem_u32(const void* p) {
    uint32_t a;
    asm("{ .reg .u64 t; cvta.to.shared.u64 t, %1; cvt.u32.u64 %0, t; }" : "=r"(a) : "l"(p));
    return a;
}

// ---------------- kernel 0 ----------------
__global__ void zero_kernel() {
    int t = threadIdx.x;
    if (t < NQ) g_cnt[t] = 0;
    if (t == 0) g_correct = 0;
}

// ---------------- kernel 1: pre-convert fp32 -> bf16 hi/lo (permuted tile layout) ----------
#define BGROUPS (KQ * 16)          // 1048576
#define AGROUPS (NQ * 16)          // 8192

__global__ void __launch_bounds__(256)
convert_kernel(const float* __restrict__ A, const float* __restrict__ B) {
    int t = blockIdx.x * 256 + threadIdx.x;
    const float* src;
    uint32_t *dh, *dl;
    if (t < BGROUPS) {
        int row = t >> 4, k16 = t & 15;
        src = B + (size_t)row * DIM + k16 * 16;
        size_t g = ((size_t)(row >> 7) * 16 + k16) * 128 + (row & 127);
        dh = g_Bh + g * 8; dl = g_Bl + g * 8;
    } else if (t < BGROUPS + AGROUPS) {
        int u = t - BGROUPS;
        int row = u >> 4, k16 = u & 15;
        src = A + (size_t)row * DIM + k16 * 16;
        size_t g = ((size_t)(row >> 7) * 16 + k16) * 128 + (row & 127);
        dh = g_Ah + g * 8; dl = g_Al + g * 8;
    } else return;

    float e[16];
    #pragma unroll
    for (int i = 0; i < 4; i++) {
        float4 v = *(const float4*)(src + i * 4);
        e[i*4+0] = v.x; e[i*4+1] = v.y; e[i*4+2] = v.z; e[i*4+3] = v.w;
    }
    uint32_t h[8], l[8];
    #pragma unroll
    for (int q = 0; q < 8; q++) {
        int p = ((q & 3) << 1) | (q >> 2);
        float x = e[2*q], y = e[2*q+1];
        __nv_bfloat162 hh = __floats2bfloat162_rn(x, y);
        float2 hf = __bfloat1622float2(hh);
        __nv_bfloat162 ll = __floats2bfloat162_rn(x - hf.x, y - hf.y);
        h[p] = *(uint32_t*)&hh; l[p] = *(uint32_t*)&ll;
    }
    *(uint4*)(dh)     = make_uint4(h[0], h[1], h[2], h[3]);
    *(uint4*)(dh + 4) = make_uint4(h[4], h[5], h[6], h[7]);
    *(uint4*)(dl)     = make_uint4(l[0], l[1], l[2], l[3]);
    *(uint4*)(dl + 4) = make_uint4(l[4], l[5], l[6], l[7]);
}

// ---------------- kernel 2: HMMA GEMM (cp.async pipelined, candidates only) -----------
#define TM 128
#define TN 128
#define NCHUNK 8
// smem: 2 stages x 4 tiles x 8KB = 64KB ; tile offsets in u32: Ah 0, Al 2048, Bh 4096, Bl 6144
#define STAGE_W 8192
#define GEMM_SMEM (2 * STAGE_W * 4)

__device__ __forceinline__ void mma16816(float* c, const uint32_t* a, const uint32_t* b) {
    asm volatile(
        "mma.sync.aligned.m16n8k16.row.col.f32.bf16.bf16.f32 "
        "{%0,%1,%2,%3}, {%4,%5,%6,%7}, {%8,%9}, {%0,%1,%2,%3};"
        : "+f"(c[0]), "+f"(c[1]), "+f"(c[2]), "+f"(c[3])
        : "r"(a[0]), "r"(a[1]), "r"(a[2]), "r"(a[3]), "r"(b[0]), "r"(b[1]));
}

__device__ __forceinline__ void cappend(int qrow, float v, int col) {
    if (v > T_FILTER) {
        int slot = atomicAdd(&g_cnt[qrow], 1);
        if (slot < CMAX)
            g_cand[(size_t)qrow * CMAX + slot] =
                ((unsigned long long)__float_as_uint(v) << 32) |
                (unsigned)(col ^ 0xFFFF);
    }
}

__global__ void __launch_bounds__(256, 2)
gemm_tc_kernel() {
    extern __shared__ uint32_t smw[];
    const uint32_t sb = smem_u32(smw);
    const int tid  = threadIdx.x;
    const int lane = tid & 31;
    const int wid  = tid >> 5;
    const int gID  = lane >> 2;
    const int tig  = lane & 3;
    const int wm   = wid >> 2;
    const int wn   = wid & 3;
    const int m_t  = blockIdx.x;        // 0..3 (fast -> B tile L2 reuse)
    const int n_t  = blockIdx.y;        // 0..511

    float acc[4][4][4];
    #pragma unroll
    for (int m = 0; m < 4; m++)
        #pragma unroll
        for (int n = 0; n < 4; n++)
            #pragma unroll
            for (int r = 0; r < 4; r++) acc[m][n][r] = 0.f;

    const uint32_t* srcA_h = g_Ah + ((size_t)m_t * 16) * 1024;
    const uint32_t* srcA_l = g_Al + ((size_t)m_t * 16) * 1024;
    const uint32_t* srcB_h = g_Bh + ((size_t)n_t * 16) * 1024;
    const uint32_t* srcB_l = g_Bl + ((size_t)n_t * 16) * 1024;

    // stage chunk ch into buffer buf: 4 tiles x 8KB contiguous each
    auto stage = [&](int ch, int buf) {
        uint32_t d0 = sb + buf * (STAGE_W * 4);
        size_t goff = (size_t)(2 * ch) * 1024;      // 2 k16-blocks = 2048 u32
        const uint32_t* s[4] = { srcA_h + goff, srcA_l + goff,
                                 srcB_h + goff, srcB_l + goff };
        #pragma unroll
        for (int tl = 0; tl < 4; tl++) {
            uint32_t d = d0 + tl * 8192 + tid * 16;
            const char* sp = (const char*)s[tl] + tid * 16;
            CP16(d, sp);
            CP16(d + 4096, sp + 4096);
        }
    };

    stage(0, 0); CPCOMMIT();
    stage(1, 1); CPCOMMIT();

    for (int ch = 0; ch < NCHUNK; ++ch) {
        asm volatile("cp.async.wait_group 1;" ::: "memory");
        __syncthreads();

        const uint32_t* stg = smw + (ch & 1) * STAGE_W;
        #pragma unroll
        for (int t = 0; t < 3; t++) {
            const uint32_t* As = stg + ((t == 2) ? 2048 : 0);
            const uint32_t* Bs = stg + 4096 + ((t == 1) ? 2048 : 0);
            #pragma unroll
            for (int s = 0; s < 2; s++) {
                uint32_t afr[4][4];
                #pragma unroll
                for (int m = 0; m < 4; m++) {
                    int row = wm * 64 + m * 16 + gID;
                    uint2 v0 = *(const uint2*)(As + (s * 128 + row) * 8 + tig * 2);
                    uint2 v1 = *(const uint2*)(As + (s * 128 + row + 8) * 8 + tig * 2);
                    afr[m][0] = v0.x; afr[m][2] = v0.y;
                    afr[m][1] = v1.x; afr[m][3] = v1.y;
                }
                uint32_t bfr[4][2];
                #pragma unroll
                for (int n = 0; n < 4; n++) {
                    int rowb = wn * 32 + n * 8 + gID;
                    uint2 v = *(const uint2*)(Bs + (s * 128 + rowb) * 8 + tig * 2);
                    bfr[n][0] = v.x; bfr[n][1] = v.y;
                }
                #pragma unroll
                for (int m = 0; m < 4; m++)
                    #pragma unroll
                    for (int n = 0; n < 4; n++)
                        mma16816(acc[m][n], afr[m], bfr[n]);
            }
        }
        __syncthreads();

        if (ch + 2 < NCHUNK) stage(ch + 2, ch & 1);
        CPCOMMIT();                      // always commit (possibly empty group)
    }

    // epilogue: candidate filter only (no sim store)
    #pragma unroll
    for (int m = 0; m < 4; m++) {
        int row = m_t * TM + wm * 64 + m * 16 + gID;
        #pragma unroll
        for (int n = 0; n < 4; n++) {
            int col = n_t * TN + wn * 32 + n * 8 + tig * 2;
            cappend(row,     acc[m][n][0], col);
            cappend(row,     acc[m][n][1], col + 1);
            cappend(row + 8, acc[m][n][2], col);
            cappend(row + 8, acc[m][n][3], col + 1);
        }
    }
}

// ---------------- kernel 3: candidate top-200 + vote + argmax (self-contained fallback) ----
#define NBINS    16384
#define CAND_MAX 1024
// smem: cand u64[CMAX] @0 (32KB) | hist u32[NBINS] @32768 (64KB) | scores @98304 (4KB)
#define TOPK_SMEM (32768 + 65536 + 4096)

__global__ void __launch_bounds__(256)
topk_kernel(const int* __restrict__ qlabels, const int* __restrict__ labels,
            const float* __restrict__ feats, const float* __restrict__ qf) {
    extern __shared__ char smem[];
    unsigned long long* cand = (unsigned long long*)smem;
    unsigned* hist = (unsigned*)(smem + 32768);
    float* scores  = (float*)(smem + 32768 + 65536);
    float* cval    = (float*)smem;                 // fallback alias
    int*   clab    = (int*)(smem + 4096);          // fallback alias
    float* fvec    = (float*)(smem + 8192);        // fallback alias (256 floats)

    __shared__ unsigned s_gsum[256];
    __shared__ int s_B, s_cGreater, s_cnt;
    __shared__ float s_bv[256];
    __shared__ int   s_bi[256];

    const int tid = threadIdx.x;
    const int q   = blockIdx.x;
    const int cnt = g_cnt[q];

    for (int i = tid; i < 1024; i += 256) scores[i] = 0.f;

    if (cnt >= KNN && cnt <= CMAX) {
        // fast path: exact stable rank over candidate set
        for (int i = tid; i < cnt; i += 256)
            cand[i] = g_cand[(size_t)q * CMAX + i];
        __syncthreads();

        for (int i = tid; i < cnt; i += 256) {
            unsigned long long mine = cand[i];
            int rank = 0;
            for (int j = 0; j < cnt; j++) rank += (cand[j] > mine);
            if (rank < KNN) {
                float v = __uint_as_float((unsigned)(mine >> 32));
                int idx = ((int)((unsigned)mine & 0xFFFFu)) ^ 0xFFFF;
                atomicAdd(&scores[qlabels[idx]], expf(v * INVT));
            }
        }
        __syncthreads();
    } else {
        // fallback (statistically unreachable): recompute this query's sims,
        // then histogram-select. Fully correct without the GEMM's sim store.
        for (int i = tid; i < DIM; i += 256) fvec[i] = feats[(size_t)q * DIM + i];
        __syncthreads();
        float* row = g_sim + (size_t)q * KQ;
        for (int i = tid; i < KQ; i += 256) {
            const float* b = qf + (size_t)i * DIM;
            float d = 0.f;
            for (int k = 0; k < DIM; k++) d = fmaf(fvec[k], b[k], d);
            row[i] = d;
        }
        __syncthreads();

        for (int i = tid; i < NBINS; i += 256) hist[i] = 0u;
        if (tid == 0) s_cnt = 0;
        __syncthreads();

        for (int i = tid; i < KQ; i += 256) {
            unsigned u = orderf(row[i]);
            atomicAdd(&hist[u >> 18], 1u);
        }
        __syncthreads();

        unsigned gs = 0;
        #pragma unroll 8
        for (int b = 0; b < 64; b++) gs += hist[tid * 64 + b];
        s_gsum[tid] = gs;
        __syncthreads();

        if (tid == 0) {
            unsigned cum = 0; int B = 0; unsigned cG = 0;
            for (int g = 255; g >= 0; --g) {
                if (cum + s_gsum[g] >= KNN) {
                    for (int b = g * 64 + 63; b >= g * 64; --b) {
                        if (cum + hist[b] >= KNN) { B = b; cG = cum; break; }
                        cum += hist[b];
                    }
                    break;
                }
                cum += s_gsum[g];
            }
            s_B = B; s_cGreater = (int)cG;
        }
        __syncthreads();

        const int B = s_B;
        int need = KNN - s_cGreater;

        for (int i = tid; i < KQ; i += 256) {
            float v = row[i];
            int bin = (int)(orderf(v) >> 18);
            if (bin > B) {
                atomicAdd(&scores[qlabels[i]], expf(v * INVT));
            } else if (bin == B) {
                int p = atomicAdd(&s_cnt, 1);
                if (p < CAND_MAX) { cval[p] = v; clab[p] = qlabels[i]; }
            }
        }
        __syncthreads();

        int bcnt = min(s_cnt, CAND_MAX);
        if (need > bcnt) need = bcnt;

        for (int i = tid; i < bcnt; i += 256) {
            float v = cval[i];
            int rank = 0;
            for (int j = 0; j < bcnt; j++) {
                float w = cval[j];
                rank += (w > v) || (w == v && j < i);
            }
            if (rank < need) atomicAdd(&scores[clab[i]], expf(v * INVT));
        }
        __syncthreads();
    }

    // argmax over 1000 classes, first-max tie-break
    float best = -1.f; int bi = NCLS;
    for (int c = tid; c < NCLS; c += 256) {
        float v = scores[c];
        if (v > best) { best = v; bi = c; }
    }
    s_bv[tid] = best; s_bi[tid] = bi;
    __syncthreads();
    for (int s = 128; s > 0; s >>= 1) {
        if (tid < s) {
            float ov = s_bv[tid + s]; int oi = s_bi[tid + s];
            if (ov > s_bv[tid] || (ov == s_bv[tid] && oi < s_bi[tid])) {
                s_bv[tid] = ov; s_bi[tid] = oi;
            }
        }
        __syncthreads();
    }
    if (tid == 0 && s_bi[0] == labels[q]) atomicAdd(&g_correct, 1);
}

// ---------------- kernel 4: queue update copy ----------------
__global__ void __launch_bounds__(256)
copy_kernel(const float* __restrict__ feats, const int* __restrict__ labels,
            const float* __restrict__ qf, const int* __restrict__ ql,
            const int* __restrict__ qptr, float* __restrict__ out) {
    const int ptr = qptr[0];
    size_t i4 = (size_t)blockIdx.x * 256 + threadIdx.x;
    if (i4 < (size_t)(NF / 4)) {
        int r = (int)(i4 >> 6);
        int rel = r - ptr; if (rel < 0) rel += KQ;
        float4 v = (rel < NQ) ? ((const float4*)feats)[(size_t)rel * 64 + (i4 & 63)]
                              : ((const float4*)qf)[i4];
        float* o = out + OUT_FEAT_OFF + i4 * 4;
        o[0] = v.x; o[1] = v.y; o[2] = v.z; o[3] = v.w;
    } else if (i4 < (size_t)(NF / 4 + NL / 4)) {
        int j4 = (int)(i4 - NF / 4);
        int4 lv = ((const int4*)ql)[j4];
        int base = j4 * 4;
        float* o = out + OUT_LAB_OFF + base;
        #pragma unroll
        for (int k = 0; k < 4; k++) {
            int i = base + k;
            int rel = i - ptr; if (rel < 0) rel += KQ;
            int lab = (rel < NQ) ? labels[rel] : ((const int*)&lv)[k];
            o[k] = (float)lab;
        }
    }
}

// ---------------- kernel 5: scalars ----------------
__global__ void finalize_kernel(const int* __restrict__ qptr, float* __restrict__ out) {
    out[0] = (float)g_correct * (1.0f / (float)NQ);
    out[OUT_PTR_OFF] = (float)((qptr[0] + NQ) % KQ);
}

// ---------------- launch ----------------
extern "C" void kernel_launch(void* const* d_in, const int* in_sizes, int n_in,
                              void* d_out, int out_size) {
    const float* feats  = (const float*)d_in[0];
    const int*   labels = (const int*)d_in[1];
    const float* qf     = (const float*)d_in[2];
    const int*   ql     = (const int*)d_in[3];
    const int*   qptr   = (const int*)d_in[4];
    float* out = (float*)d_out;

    cudaFuncSetAttribute(gemm_tc_kernel, cudaFuncAttributeMaxDynamicSharedMemorySize, GEMM_SMEM);
    cudaFuncSetAttribute(topk_kernel, cudaFuncAttributeMaxDynamicSharedMemorySize, TOPK_SMEM);

    zero_kernel<<<1, 512>>>();
    convert_kernel<<<(BGROUPS + AGROUPS + 255) / 256, 256>>>(feats, qf);
    gemm_tc_kernel<<<dim3(NQ / TM, KQ / TN), 256, GEMM_SMEM>>>();
    topk_kernel<<<NQ, 256, TOPK_SMEM>>>(ql, labels, feats, qf);

    int total4 = NF / 4 + NL / 4;
    copy_kernel<<<(total4 + 255) / 256, 256>>>(feats, labels, qf, ql, qptr, out);
    finalize_kernel<<<1, 1>>>(qptr, out);
    (void)in_sizes; (void)n_in; (void)out_size;
}

// round 6
// speedup vs baseline: 1.7059x; 1.3077x over previous
#include <cuda_runtime.h>
#include <cuda_bf16.h>
#include <math.h>
#include <cstdint>

// ---------------- problem constants ----------------
#define NQ      512
#define DIM     256
#define KQ      65536
#define KNN     200
#define NCLS    1000
#define INVT    (1.0f/0.07f)

#define NF      (KQ*DIM)
#define NL      KQ

#define OUT_FEAT_OFF 1
#define OUT_LAB_OFF  (1 + NF)
#define OUT_PTR_OFF  (1 + NF + NL)

// candidate filtering
#define CMAX     4096
#define T_FILTER 0.14f

// ---------------- device scratch ----------------
__device__ float g_sim[(size_t)NQ * KQ];                 // fallback scratch only
__device__ unsigned long long g_cand[(size_t)NQ * CMAX];
__device__ int  g_cnt[NQ];
__device__ int  g_correct;

// pre-converted bf16 hi/lo operands, tile-sequential permuted layout
__device__ uint32_t g_Ah[65536],  g_Al[65536];
__device__ uint32_t g_Bh[(size_t)8388608], g_Bl[(size_t)8388608];

__device__ __forceinline__ unsigned orderf(float f) {
    unsigned u = __float_as_uint(f);
    return (u & 0x80000000u) ? ~u : (u | 0x80000000u);
}
__device__ __forceinline__ float unorderf(unsigned k) {
    return __uint_as_float((k & 0x80000000u) ? (k ^ 0x80000000u) : ~k);
}

#define CP16(dst, src) \
    asm volatile("cp.async.cg.shared.global [%0], [%1], 16;" :: "r"(dst), "l"(src) : "memory")
#define CPCOMMIT() asm volatile("cp.async.commit_group;" ::: "memory")

__device__ __forceinline__ uint32_t smem_u32(const void* p) {
    uint32_t a;
    asm("{ .reg .u64 t; cvta.to.shared.u64 t, %1; cvt.u32.u64 %0, t; }" : "=r"(a) : "l"(p));
    return a;
}

// ---------------- kernel 0 ----------------
__global__ void zero_kernel() {
    int t = threadIdx.x;
    if (t < NQ) g_cnt[t] = 0;
    if (t == 0) g_correct = 0;
}

// ---------------- kernel 1: pre-convert fp32 -> bf16 hi/lo ----------
#define BGROUPS (KQ * 16)
#define AGROUPS (NQ * 16)

__global__ void __launch_bounds__(256)
convert_kernel(const float* __restrict__ A, const float* __restrict__ B) {
    int t = blockIdx.x * 256 + threadIdx.x;
    const float* src;
    uint32_t *dh, *dl;
    if (t < BGROUPS) {
        int row = t >> 4, k16 = t & 15;
        src = B + (size_t)row * DIM + k16 * 16;
        size_t g = ((size_t)(row >> 7) * 16 + k16) * 128 + (row & 127);
        dh = g_Bh + g * 8; dl = g_Bl + g * 8;
    } else if (t < BGROUPS + AGROUPS) {
        int u = t - BGROUPS;
        int row = u >> 4, k16 = u & 15;
        src = A + (size_t)row * DIM + k16 * 16;
        size_t g = ((size_t)(row >> 7) * 16 + k16) * 128 + (row & 127);
        dh = g_Ah + g * 8; dl = g_Al + g * 8;
    } else return;

    float e[16];
    #pragma unroll
    for (int i = 0; i < 4; i++) {
        float4 v = *(const float4*)(src + i * 4);
        e[i*4+0] = v.x; e[i*4+1] = v.y; e[i*4+2] = v.z; e[i*4+3] = v.w;
    }
    uint32_t h[8], l[8];
    #pragma unroll
    for (int q = 0; q < 8; q++) {
        int p = ((q & 3) << 1) | (q >> 2);
        float x = e[2*q], y = e[2*q+1];
        __nv_bfloat162 hh = __floats2bfloat162_rn(x, y);
        float2 hf = __bfloat1622float2(hh);
        __nv_bfloat162 ll = __floats2bfloat162_rn(x - hf.x, y - hf.y);
        h[p] = *(uint32_t*)&hh; l[p] = *(uint32_t*)&ll;
    }
    *(uint4*)(dh)     = make_uint4(h[0], h[1], h[2], h[3]);
    *(uint4*)(dh + 4) = make_uint4(h[4], h[5], h[6], h[7]);
    *(uint4*)(dl)     = make_uint4(l[0], l[1], l[2], l[3]);
    *(uint4*)(dl + 4) = make_uint4(l[4], l[5], l[6], l[7]);
}

// ---------------- kernel 2: HMMA GEMM (cp.async pipelined, candidates only) -----------
#define TM 128
#define TN 128
#define NCHUNK 8
#define STAGE_W 8192
#define GEMM_SMEM (2 * STAGE_W * 4)

__device__ __forceinline__ void mma16816(float* c, const uint32_t* a, const uint32_t* b) {
    asm volatile(
        "mma.sync.aligned.m16n8k16.row.col.f32.bf16.bf16.f32 "
        "{%0,%1,%2,%3}, {%4,%5,%6,%7}, {%8,%9}, {%0,%1,%2,%3};"
        : "+f"(c[0]), "+f"(c[1]), "+f"(c[2]), "+f"(c[3])
        : "r"(a[0]), "r"(a[1]), "r"(a[2]), "r"(a[3]), "r"(b[0]), "r"(b[1]));
}

__device__ __forceinline__ void cappend(int qrow, float v, int col) {
    if (v > T_FILTER) {
        int slot = atomicAdd(&g_cnt[qrow], 1);
        if (slot < CMAX)
            g_cand[(size_t)qrow * CMAX + slot] =
                ((unsigned long long)__float_as_uint(v) << 32) |
                (unsigned)(col ^ 0xFFFF);
    }
}

__global__ void __launch_bounds__(256, 2)
gemm_tc_kernel() {
    extern __shared__ uint32_t smw[];
    const uint32_t sb = smem_u32(smw);
    const int tid  = threadIdx.x;
    const int lane = tid & 31;
    const int wid  = tid >> 5;
    const int gID  = lane >> 2;
    const int tig  = lane & 3;
    const int wm   = wid >> 2;
    const int wn   = wid & 3;
    const int m_t  = blockIdx.x;
    const int n_t  = blockIdx.y;

    float acc[4][4][4];
    #pragma unroll
    for (int m = 0; m < 4; m++)
        #pragma unroll
        for (int n = 0; n < 4; n++)
            #pragma unroll
            for (int r = 0; r < 4; r++) acc[m][n][r] = 0.f;

    const uint32_t* srcA_h = g_Ah + ((size_t)m_t * 16) * 1024;
    const uint32_t* srcA_l = g_Al + ((size_t)m_t * 16) * 1024;
    const uint32_t* srcB_h = g_Bh + ((size_t)n_t * 16) * 1024;
    const uint32_t* srcB_l = g_Bl + ((size_t)n_t * 16) * 1024;

    auto stage = [&](int ch, int buf) {
        uint32_t d0 = sb + buf * (STAGE_W * 4);
        size_t goff = (size_t)(2 * ch) * 1024;
        const uint32_t* s[4] = { srcA_h + goff, srcA_l + goff,
                                 srcB_h + goff, srcB_l + goff };
        #pragma unroll
        for (int tl = 0; tl < 4; tl++) {
            uint32_t d = d0 + tl * 8192 + tid * 16;
            const char* sp = (const char*)s[tl] + tid * 16;
            CP16(d, sp);
            CP16(d + 4096, sp + 4096);
        }
    };

    stage(0, 0); CPCOMMIT();
    stage(1, 1); CPCOMMIT();

    for (int ch = 0; ch < NCHUNK; ++ch) {
        asm volatile("cp.async.wait_group 1;" ::: "memory");
        __syncthreads();

        const uint32_t* stg = smw + (ch & 1) * STAGE_W;
        #pragma unroll
        for (int t = 0; t < 3; t++) {
            const uint32_t* As = stg + ((t == 2) ? 2048 : 0);
            const uint32_t* Bs = stg + 4096 + ((t == 1) ? 2048 : 0);
            #pragma unroll
            for (int s = 0; s < 2; s++) {
                uint32_t afr[4][4];
                #pragma unroll
                for (int m = 0; m < 4; m++) {
                    int row = wm * 64 + m * 16 + gID;
                    uint2 v0 = *(const uint2*)(As + (s * 128 + row) * 8 + tig * 2);
                    uint2 v1 = *(const uint2*)(As + (s * 128 + row + 8) * 8 + tig * 2);
                    afr[m][0] = v0.x; afr[m][2] = v0.y;
                    afr[m][1] = v1.x; afr[m][3] = v1.y;
                }
                uint32_t bfr[4][2];
                #pragma unroll
                for (int n = 0; n < 4; n++) {
                    int rowb = wn * 32 + n * 8 + gID;
                    uint2 v = *(const uint2*)(Bs + (s * 128 + rowb) * 8 + tig * 2);
                    bfr[n][0] = v.x; bfr[n][1] = v.y;
                }
                #pragma unroll
                for (int m = 0; m < 4; m++)
                    #pragma unroll
                    for (int n = 0; n < 4; n++)
                        mma16816(acc[m][n], afr[m], bfr[n]);
            }
        }
        __syncthreads();

        if (ch + 2 < NCHUNK) stage(ch + 2, ch & 1);
        CPCOMMIT();
    }

    #pragma unroll
    for (int m = 0; m < 4; m++) {
        int row = m_t * TM + wm * 64 + m * 16 + gID;
        #pragma unroll
        for (int n = 0; n < 4; n++) {
            int col = n_t * TN + wn * 32 + n * 8 + tig * 2;
            cappend(row,     acc[m][n][0], col);
            cappend(row,     acc[m][n][1], col + 1);
            cappend(row + 8, acc[m][n][2], col);
            cappend(row + 8, acc[m][n][3], col + 1);
        }
    }
}

// ---------------- kernel 3: O(cnt) top-200 via histogram + vote + argmax ----------------
#define TK_BINS 2048
#define BND_MAX 1024
// smem: cand u64[CMAX] @0 (32KB) | hist u32[2048] @32768 (8KB) | scores f32[1024] @40960 (4KB)
#define TOPK_SMEM (32768 + 8192 + 4096)

__global__ void __launch_bounds__(256)
topk_kernel(const int* __restrict__ qlabels, const int* __restrict__ labels,
            const float* __restrict__ feats, const float* __restrict__ qf) {
    extern __shared__ char smem[];
    unsigned long long* cand = (unsigned long long*)smem;
    unsigned* hist = (unsigned*)(smem + 32768);
    float* scores  = (float*)(smem + 32768 + 8192);

    __shared__ unsigned long long bnd[BND_MAX];
    __shared__ unsigned s_gsum[256];
    __shared__ int s_B, s_cGreater, s_bcnt;
    __shared__ float s_bv[256];
    __shared__ int   s_bi[256];

    const int tid = threadIdx.x;
    const int q   = blockIdx.x;
    int cnt = g_cnt[q];
    const bool fast = (cnt >= KNN && cnt <= CMAX);

    for (int i = tid; i < 1024; i += 256) scores[i] = 0.f;
    for (int i = tid; i < TK_BINS; i += 256) hist[i] = 0u;
    if (tid == 0) s_bcnt = 0;

    if (fast) {
        // load candidates (value bits are positive floats > 0.14)
        for (int i = tid; i < cnt; i += 256)
            cand[i] = g_cand[(size_t)q * CMAX + i];
        __syncthreads();

        // histogram on high value bits
        for (int i = tid; i < cnt; i += 256) {
            unsigned bits = (unsigned)(cand[i] >> 32);
            int bin = min((int)((bits - 0x3E000000u) >> 14), TK_BINS - 1);
            atomicAdd(&hist[bin], 1u);
        }
    } else {
        // fallback (statistically unreachable): recompute sims for this query
        float* fvec = (float*)bnd;   // temp reuse (256 floats < 8KB)
        for (int i = tid; i < DIM; i += 256) fvec[i] = feats[(size_t)q * DIM + i];
        __syncthreads();
        float* row = g_sim + (size_t)q * KQ;
        for (int i = tid; i < KQ; i += 256) {
            const float4* b4 = (const float4*)(qf + (size_t)i * DIM);
            float d = 0.f;
            #pragma unroll 8
            for (int k = 0; k < DIM / 4; k++) {
                float4 bv = b4[k];
                d = fmaf(fvec[4*k+0], bv.x, d);
                d = fmaf(fvec[4*k+1], bv.y, d);
                d = fmaf(fvec[4*k+2], bv.z, d);
                d = fmaf(fvec[4*k+3], bv.w, d);
            }
            row[i] = d;
        }
        __syncthreads();
        // repack full row into "candidates = everything" form is too big;
        // histogram orderf keys directly
        for (int i = tid; i < KQ; i += 256)
            atomicAdd(&hist[orderf(row[i]) >> 21], 1u);
        cnt = -1;   // marker: candidate array not used
    }
    __syncthreads();

    // two-level scan for threshold bin (bins descending = values descending)
    unsigned gs = 0;
    #pragma unroll 8
    for (int b = 0; b < 8; b++) gs += hist[tid * 8 + b];
    s_gsum[tid] = gs;
    __syncthreads();

    if (tid == 0) {
        unsigned cum = 0; int B = 0; unsigned cG = 0;
        for (int g = 255; g >= 0; --g) {
            if (cum + s_gsum[g] >= KNN) {
                for (int b = g * 8 + 7; b >= g * 8; --b) {
                    if (cum + hist[b] >= KNN) { B = b; cG = cum; break; }
                    cum += hist[b];
                }
                break;
            }
            cum += s_gsum[g];
        }
        s_B = B; s_cGreater = (int)cG;
    }
    __syncthreads();

    const int B = s_B;
    int need = KNN - s_cGreater;

    if (fast) {
        const int n0 = g_cnt[q];
        for (int i = tid; i < n0; i += 256) {
            unsigned long long c = cand[i];
            unsigned bits = (unsigned)(c >> 32);
            int bin = min((int)((bits - 0x3E000000u) >> 14), TK_BINS - 1);
            if (bin > B) {
                int idx = ((int)((unsigned)c & 0xFFFFu)) ^ 0xFFFF;
                atomicAdd(&scores[qlabels[idx]], expf(__uint_as_float(bits) * INVT));
            } else if (bin == B) {
                int p = atomicAdd(&s_bcnt, 1);
                if (p < BND_MAX) bnd[p] = c;
            }
        }
    } else {
        const float* row = g_sim + (size_t)q * KQ;
        for (int i = tid; i < KQ; i += 256) {
            float v = row[i];
            unsigned k = orderf(v);
            int bin = (int)(k >> 21);
            if (bin > B) {
                atomicAdd(&scores[qlabels[i]], expf(v * INVT));
            } else if (bin == B) {
                int p = atomicAdd(&s_bcnt, 1);
                if (p < BND_MAX)
                    bnd[p] = ((unsigned long long)k << 32) | (unsigned)(i ^ 0xFFFF);
            }
        }
    }
    __syncthreads();

    // exact stable rank within tiny boundary bin
    int bcnt = min(s_bcnt, BND_MAX);
    if (need > bcnt) need = bcnt;
    for (int i = tid; i < bcnt; i += 256) {
        unsigned long long mine = bnd[i];
        int rank = 0;
        for (int j = 0; j < bcnt; j++) rank += (bnd[j] > mine);
        if (rank < need) {
            unsigned hi = (unsigned)(mine >> 32);
            float v = fast ? __uint_as_float(hi) : unorderf(hi);
            int idx = ((int)((unsigned)mine & 0xFFFFu)) ^ 0xFFFF;
            atomicAdd(&scores[qlabels[idx]], expf(v * INVT));
        }
    }
    __syncthreads();

    // argmax over 1000 classes, first-max tie-break
    float best = -1.f; int bi = NCLS;
    for (int c = tid; c < NCLS; c += 256) {
        float v = scores[c];
        if (v > best) { best = v; bi = c; }
    }
    s_bv[tid] = best; s_bi[tid] = bi;
    __syncthreads();
    for (int s = 128; s > 0; s >>= 1) {
        if (tid < s) {
            float ov = s_bv[tid + s]; int oi = s_bi[tid + s];
            if (ov > s_bv[tid] || (ov == s_bv[tid] && oi < s_bi[tid])) {
                s_bv[tid] = ov; s_bi[tid] = oi;
            }
        }
        __syncthreads();
    }
    if (tid == 0 && s_bi[0] == labels[q]) atomicAdd(&g_correct, 1);
}

// ---------------- kernel 4: queue update copy ----------------
__global__ void __launch_bounds__(256)
copy_kernel(const float* __restrict__ feats, const int* __restrict__ labels,
            const float* __restrict__ qf, const int* __restrict__ ql,
            const int* __restrict__ qptr, float* __restrict__ out) {
    const int ptr = qptr[0];
    size_t i4 = (size_t)blockIdx.x * 256 + threadIdx.x;
    if (i4 < (size_t)(NF / 4)) {
        int r = (int)(i4 >> 6);
        int rel = r - ptr; if (rel < 0) rel += KQ;
        float4 v = (rel < NQ) ? ((const float4*)feats)[(size_t)rel * 64 + (i4 & 63)]
                              : ((const float4*)qf)[i4];
        float* o = out + OUT_FEAT_OFF + i4 * 4;
        o[0] = v.x; o[1] = v.y; o[2] = v.z; o[3] = v.w;
    } else if (i4 < (size_t)(NF / 4 + NL / 4)) {
        int j4 = (int)(i4 - NF / 4);
        int4 lv = ((const int4*)ql)[j4];
        int base = j4 * 4;
        float* o = out + OUT_LAB_OFF + base;
        #pragma unroll
        for (int k = 0; k < 4; k++) {
            int i = base + k;
            int rel = i - ptr; if (rel < 0) rel += KQ;
            int lab = (rel < NQ) ? labels[rel] : ((const int*)&lv)[k];
            o[k] = (float)lab;
        }
    }
}

// ---------------- kernel 5: scalars ----------------
__global__ void finalize_kernel(const int* __restrict__ qptr, float* __restrict__ out) {
    out[0] = (float)g_correct * (1.0f / (float)NQ);
    out[OUT_PTR_OFF] = (float)((qptr[0] + NQ) % KQ);
}

// ---------------- launch ----------------
extern "C" void kernel_launch(void* const* d_in, const int* in_sizes, int n_in,
                              void* d_out, int out_size) {
    const float* feats  = (const float*)d_in[0];
    const int*   labels = (const int*)d_in[1];
    const float* qf     = (const float*)d_in[2];
    const int*   ql     = (const int*)d_in[3];
    const int*   qptr   = (const int*)d_in[4];
    float* out = (float*)d_out;

    cudaFuncSetAttribute(gemm_tc_kernel, cudaFuncAttributeMaxDynamicSharedMemorySize, GEMM_SMEM);
    cudaFuncSetAttribute(topk_kernel, cudaFuncAttributeMaxDynamicSharedMemorySize, TOPK_SMEM);

    zero_kernel<<<1, 512>>>();
    convert_kernel<<<(BGROUPS + AGROUPS + 255) / 256, 256>>>(feats, qf);
    gemm_tc_kernel<<<dim3(NQ / TM, KQ / TN), 256, GEMM_SMEM>>>();
    topk_kernel<<<NQ, 256, TOPK_SMEM>>>(ql, labels, feats, qf);

    int total4 = NF / 4 + NL / 4;
    copy_kernel<<<(total4 + 255) / 256, 256>>>(feats, labels, qf, ql, qptr, out);
    finalize_kernel<<<1, 1>>>(qptr, out);
    (void)in_sizes; (void)n_in; (void)out_size;
}